// round 1
// baseline (speedup 1.0000x reference)
#include <cuda_runtime.h>
#include <math.h>

#define CC   256
#define CQ   32
#define NPIX 4096
#define EPSB 1e-5f

// ---------------- scratch (static device arrays; no allocation) ----------------
__device__ float g_xf1[CC * NPIX];
__device__ float g_xf2[CC * NPIX];
__device__ float g_qb[CQ * NPIX];
__device__ float g_kb[CQ * NPIX];
__device__ float g_vb[CC * NPIX];
__device__ float g_attn[(size_t)NPIX * NPIX];   // 64 MB

// ---------------------------------------------------------------------------
// Fused dual conv3x3 + eval-BN + magnitude:
//   out[o,p] = sqrt( bnX(convX(x))^2 + bnY(convY(x))^2 )
// GEMM view: M=256 (out ch), N=4096 (pixels), K=9*256 ordered k = tap*256 + ci.
// BN(block)=64 == image width, so each block covers exactly one image row.
// grid (64, 4), block 256.
// ---------------------------------------------------------------------------
__global__ void sobel_kernel(const float* __restrict__ x,
                             const float* __restrict__ wx,
                             const float* __restrict__ wy,
                             const float* __restrict__ bnx,
                             const float* __restrict__ bny,
                             float* __restrict__ out)
{
    __shared__ float Ax[64][17];
    __shared__ float Ay[64][17];
    __shared__ float Bs[16][64];

    const int tid = threadIdx.x;
    const int tx = tid & 15, ty = tid >> 4;
    const int m0 = blockIdx.y * 64;
    const int n0 = blockIdx.x * 64;      // = row_y * 64
    const int row_y = blockIdx.x;

    float accx[4][4] = {};
    float accy[4][4] = {};

    for (int kt = 0; kt < 9 * 256; kt += 16) {
        const int tap = kt >> 8;                 // constant over this 16-slice
        const int dy = tap / 3 - 1;
        const int dx = tap % 3 - 1;

        // weights: w[o, ci, ky, kx] -> A[o][k], k = tap*256 + ci
        #pragma unroll
        for (int r = 0; r < 4; r++) {
            int idx = tid + r * 256;             // 0..1023
            int am = idx >> 4, ak = idx & 15;
            int k  = kt + ak;
            int ci = k & 255;
            int tp = k >> 8;
            int widx = (m0 + am) * 2304 + ci * 9 + tp;
            Ax[am][ak] = wx[widx];
            Ay[am][ak] = wy[widx];
        }
        // shifted input tile: B[kk][n] = x[ci, row_y+dy, n+dx] (0 at borders)
        {
            const int yy = row_y + dy;
            const bool yok = (yy >= 0) && (yy < 64);
            #pragma unroll
            for (int r = 0; r < 4; r++) {
                int idx = tid + r * 256;
                int bk = idx >> 6, bn = idx & 63;
                int ci = (kt + bk) & 255;
                int xx = bn + dx;
                float v = 0.f;
                if (yok && xx >= 0 && xx < 64)
                    v = x[ci * NPIX + yy * 64 + xx];
                Bs[bk][bn] = v;
            }
        }
        __syncthreads();

        #pragma unroll
        for (int kk = 0; kk < 16; kk++) {
            float ax[4], ay[4], b[4];
            #pragma unroll
            for (int i = 0; i < 4; i++) { ax[i] = Ax[ty*4+i][kk]; ay[i] = Ay[ty*4+i][kk]; }
            #pragma unroll
            for (int j = 0; j < 4; j++) b[j] = Bs[kk][tx*4+j];
            #pragma unroll
            for (int i = 0; i < 4; i++)
                #pragma unroll
                for (int j = 0; j < 4; j++) {
                    accx[i][j] += ax[i] * b[j];
                    accy[i][j] += ay[i] * b[j];
                }
        }
        __syncthreads();
    }

    #pragma unroll
    for (int i = 0; i < 4; i++) {
        const int m = m0 + ty * 4 + i;
        const float invx = bnx[m] * rsqrtf(bnx[768 + m] + EPSB);
        const float bx_  = bnx[256 + m];
        const float mx_  = bnx[512 + m];
        const float invy = bny[m] * rsqrtf(bny[768 + m] + EPSB);
        const float by_  = bny[256 + m];
        const float my_  = bny[512 + m];
        #pragma unroll
        for (int j = 0; j < 4; j++) {
            const int n = n0 + tx * 4 + j;
            float a = (accx[i][j] - mx_) * invx + bx_;
            float b = (accy[i][j] - my_) * invy + by_;
            out[m * NPIX + n] = sqrtf(a * a + b * b);
        }
    }
}

// ---------------------------------------------------------------------------
// out[M][4096] = A[M][256] * B[256][4096] + bias[M]   (M = 32 or 256)
// grid (64, ceil(M/64)), block 256.
// ---------------------------------------------------------------------------
__global__ void gemm_bias_kernel(const float* __restrict__ A,
                                 const float* __restrict__ B,
                                 const float* __restrict__ bias,
                                 float* __restrict__ out,
                                 int M)
{
    __shared__ float As[64][17];
    __shared__ float Bs[16][64];
    const int tid = threadIdx.x;
    const int tx = tid & 15, ty = tid >> 4;
    const int m0 = blockIdx.y * 64, n0 = blockIdx.x * 64;
    float acc[4][4] = {};

    for (int kt = 0; kt < 256; kt += 16) {
        #pragma unroll
        for (int r = 0; r < 4; r++) {
            int idx = tid + r * 256;
            int am = idx >> 4, ak = idx & 15;
            int m = m0 + am;
            As[am][ak] = (m < M) ? A[m * 256 + kt + ak] : 0.f;
        }
        #pragma unroll
        for (int r = 0; r < 4; r++) {
            int idx = tid + r * 256;
            int bk = idx >> 6, bn = idx & 63;
            Bs[bk][bn] = B[(kt + bk) * NPIX + n0 + bn];
        }
        __syncthreads();
        #pragma unroll
        for (int kk = 0; kk < 16; kk++) {
            float a[4], b[4];
            #pragma unroll
            for (int i = 0; i < 4; i++) a[i] = As[ty*4+i][kk];
            #pragma unroll
            for (int j = 0; j < 4; j++) b[j] = Bs[kk][tx*4+j];
            #pragma unroll
            for (int i = 0; i < 4; i++)
                #pragma unroll
                for (int j = 0; j < 4; j++)
                    acc[i][j] += a[i] * b[j];
        }
        __syncthreads();
    }

    #pragma unroll
    for (int i = 0; i < 4; i++) {
        int m = m0 + ty * 4 + i;
        if (m < M) {
            float bb = bias[m];
            #pragma unroll
            for (int j = 0; j < 4; j++)
                out[m * NPIX + n0 + tx * 4 + j] = acc[i][j] + bb;
        }
    }
}

// ---------------------------------------------------------------------------
// energy[m][n] = sum_{c<32} q[c][m] * k[c][n]   (full K in smem)
// grid (64, 64), block 256.
// ---------------------------------------------------------------------------
__global__ void energy_kernel(const float* __restrict__ q,
                              const float* __restrict__ k,
                              float* __restrict__ e)
{
    __shared__ float As[32][64];
    __shared__ float Bs[32][64];
    const int tid = threadIdx.x;
    const int tx = tid & 15, ty = tid >> 4;
    const int m0 = blockIdx.y * 64, n0 = blockIdx.x * 64;

    #pragma unroll
    for (int r = 0; r < 8; r++) {
        int idx = tid + r * 256;
        int c = idx >> 6, mm = idx & 63;
        As[c][mm] = q[c * NPIX + m0 + mm];
        Bs[c][mm] = k[c * NPIX + n0 + mm];
    }
    __syncthreads();

    float acc[4][4] = {};
    #pragma unroll
    for (int c = 0; c < 32; c++) {
        float a[4], b[4];
        #pragma unroll
        for (int i = 0; i < 4; i++) a[i] = As[c][ty*4+i];
        #pragma unroll
        for (int j = 0; j < 4; j++) b[j] = Bs[c][tx*4+j];
        #pragma unroll
        for (int i = 0; i < 4; i++)
            #pragma unroll
            for (int j = 0; j < 4; j++)
                acc[i][j] += a[i] * b[j];
    }
    #pragma unroll
    for (int i = 0; i < 4; i++)
        #pragma unroll
        for (int j = 0; j < 4; j++)
            e[(size_t)(m0 + ty*4 + i) * NPIX + n0 + tx*4 + j] = acc[i][j];
}

// ---------------------------------------------------------------------------
// In-place row softmax over 4096 columns. grid 4096, block 256.
// ---------------------------------------------------------------------------
__global__ void softmax_kernel(float* __restrict__ e)
{
    __shared__ float red[8];
    float4* p = (float4*)(e + (size_t)blockIdx.x * NPIX);
    const int tid = threadIdx.x;
    float4 v[4];
    float mx = -1e30f;
    #pragma unroll
    for (int r = 0; r < 4; r++) {
        v[r] = p[tid + r * 256];
        mx = fmaxf(mx, fmaxf(fmaxf(v[r].x, v[r].y), fmaxf(v[r].z, v[r].w)));
    }
    #pragma unroll
    for (int o = 16; o > 0; o >>= 1)
        mx = fmaxf(mx, __shfl_xor_sync(0xffffffffu, mx, o));
    if ((tid & 31) == 0) red[tid >> 5] = mx;
    __syncthreads();
    mx = red[0];
    #pragma unroll
    for (int w = 1; w < 8; w++) mx = fmaxf(mx, red[w]);
    __syncthreads();

    float s = 0.f;
    #pragma unroll
    for (int r = 0; r < 4; r++) {
        v[r].x = __expf(v[r].x - mx); s += v[r].x;
        v[r].y = __expf(v[r].y - mx); s += v[r].y;
        v[r].z = __expf(v[r].z - mx); s += v[r].z;
        v[r].w = __expf(v[r].w - mx); s += v[r].w;
    }
    #pragma unroll
    for (int o = 16; o > 0; o >>= 1)
        s += __shfl_xor_sync(0xffffffffu, s, o);
    if ((tid & 31) == 0) red[tid >> 5] = s;
    __syncthreads();
    s = 0.f;
    #pragma unroll
    for (int w = 0; w < 8; w++) s += red[w];
    const float inv = 1.f / s;
    #pragma unroll
    for (int r = 0; r < 4; r++) {
        v[r].x *= inv; v[r].y *= inv; v[r].z *= inv; v[r].w *= inv;
        p[tid + r * 256] = v[r];
    }
}

// ---------------------------------------------------------------------------
// out[m][n] = gamma * sum_k v[m][k] * attn[n][k] + xq[m][n]
// M=256, N=4096, K=4096.  B tile loaded transposed (coalesced along k).
// grid (64, 4), block 256.
// ---------------------------------------------------------------------------
__global__ void av_kernel(const float* __restrict__ vmat,
                          const float* __restrict__ attn,
                          const float* __restrict__ xq,
                          const float* __restrict__ gamma,
                          float* __restrict__ out)
{
    __shared__ float As[64][33];
    __shared__ float Bs[32][65];
    const int tid = threadIdx.x;
    const int tx = tid & 15, ty = tid >> 4;
    const int m0 = blockIdx.y * 64, n0 = blockIdx.x * 64;
    float acc[4][4] = {};

    for (int kt = 0; kt < NPIX; kt += 32) {
        #pragma unroll
        for (int r = 0; r < 8; r++) {
            int idx = tid + r * 256;
            int am = idx >> 5, ak = idx & 31;
            As[am][ak] = vmat[(m0 + am) * NPIX + kt + ak];
        }
        #pragma unroll
        for (int r = 0; r < 8; r++) {
            int idx = tid + r * 256;
            int bn = idx >> 5, bk = idx & 31;
            Bs[bk][bn] = attn[(size_t)(n0 + bn) * NPIX + kt + bk];
        }
        __syncthreads();
        #pragma unroll
        for (int kk = 0; kk < 32; kk++) {
            float a[4], b[4];
            #pragma unroll
            for (int i = 0; i < 4; i++) a[i] = As[ty*4+i][kk];
            #pragma unroll
            for (int j = 0; j < 4; j++) b[j] = Bs[kk][tx*4+j];
            #pragma unroll
            for (int i = 0; i < 4; i++)
                #pragma unroll
                for (int j = 0; j < 4; j++)
                    acc[i][j] += a[i] * b[j];
        }
        __syncthreads();
    }

    const float g = gamma[0];
    #pragma unroll
    for (int i = 0; i < 4; i++) {
        const int m = m0 + ty * 4 + i;
        #pragma unroll
        for (int j = 0; j < 4; j++) {
            const int n = n0 + tx * 4 + j;
            out[m * NPIX + n] = g * acc[i][j] + xq[m * NPIX + n];
        }
    }
}

// ---------------------------------------------------------------------------
extern "C" void kernel_launch(void* const* d_in, const int* in_sizes, int n_in,
                              void* d_out, int out_size)
{
    const float* x1    = (const float*)d_in[0];
    const float* x2    = (const float*)d_in[1];
    const float* sx1_w = (const float*)d_in[2];
    const float* sy1_w = (const float*)d_in[3];
    const float* bn1x  = (const float*)d_in[4];
    const float* bn1y  = (const float*)d_in[5];
    const float* sx2_w = (const float*)d_in[6];
    const float* sy2_w = (const float*)d_in[7];
    const float* bn2x  = (const float*)d_in[8];
    const float* bn2y  = (const float*)d_in[9];
    const float* q1_w  = (const float*)d_in[10];
    const float* q1_b  = (const float*)d_in[11];
    const float* k1_w  = (const float*)d_in[12];
    const float* k1_b  = (const float*)d_in[13];
    const float* v1_w  = (const float*)d_in[14];
    const float* v1_b  = (const float*)d_in[15];
    const float* q2_w  = (const float*)d_in[16];
    const float* q2_b  = (const float*)d_in[17];
    const float* k2_w  = (const float*)d_in[18];
    const float* k2_b  = (const float*)d_in[19];
    const float* v2_w  = (const float*)d_in[20];
    const float* v2_b  = (const float*)d_in[21];
    const float* gamma1 = (const float*)d_in[22];
    const float* gamma2 = (const float*)d_in[23];
    float* out = (float*)d_out;

    float *xf1, *xf2, *qb, *kb, *vb, *attn;
    cudaGetSymbolAddress((void**)&xf1, g_xf1);
    cudaGetSymbolAddress((void**)&xf2, g_xf2);
    cudaGetSymbolAddress((void**)&qb,  g_qb);
    cudaGetSymbolAddress((void**)&kb,  g_kb);
    cudaGetSymbolAddress((void**)&vb,  g_vb);
    cudaGetSymbolAddress((void**)&attn, g_attn);

    dim3 blk(256);

    sobel_kernel<<<dim3(64, 4), blk>>>(x1, sx1_w, sy1_w, bn1x, bn1y, xf1);
    sobel_kernel<<<dim3(64, 4), blk>>>(x2, sx2_w, sy2_w, bn2x, bn2y, xf2);

    // ---- attention 1: q from x1, k/v from xf2 -> out1 ----
    gemm_bias_kernel<<<dim3(64, 1), blk>>>(q1_w, x1,  q1_b, qb, CQ);
    gemm_bias_kernel<<<dim3(64, 1), blk>>>(k1_w, xf2, k1_b, kb, CQ);
    gemm_bias_kernel<<<dim3(64, 4), blk>>>(v1_w, xf2, v1_b, vb, CC);
    energy_kernel<<<dim3(64, 64), blk>>>(qb, kb, attn);
    softmax_kernel<<<NPIX, 256>>>(attn);
    av_kernel<<<dim3(64, 4), blk>>>(vb, attn, x1, gamma1, out);

    // ---- attention 2: q from x2, k/v from xf1 -> out2 ----
    gemm_bias_kernel<<<dim3(64, 1), blk>>>(q2_w, x2,  q2_b, qb, CQ);
    gemm_bias_kernel<<<dim3(64, 1), blk>>>(k2_w, xf1, k2_b, kb, CQ);
    gemm_bias_kernel<<<dim3(64, 4), blk>>>(v2_w, xf1, v2_b, vb, CC);
    energy_kernel<<<dim3(64, 64), blk>>>(qb, kb, attn);
    softmax_kernel<<<NPIX, 256>>>(attn);
    av_kernel<<<dim3(64, 4), blk>>>(vb, attn, x2, gamma2, out + CC * NPIX);
}